// round 13
// baseline (speedup 1.0000x reference)
#include <cuda_runtime.h>
#include <math.h>
#include <float.h>
#include <stdint.h>

#define B_ 4
#define T_ 24
#define N_ 1024
#define F_ 128
#define H_ (B_*T_)
#define FRONT_T_ 12
#define ROWS_TOT (H_*N_)
#define LDP 132
#define EPS_ 1e-5f

__device__ __align__(128) float g_Q[(size_t)H_*N_*F_];
__device__ __align__(128) float g_K[(size_t)H_*N_*F_];
__device__ __align__(128) float g_V[(size_t)H_*N_*F_];
__device__ __align__(128) float g_AO[(size_t)H_*N_*F_];
__device__ float g_colsum[B_*N_];
__device__ int g_ylast[B_];

// ---- mma.sync m16n8k8 tf32 (verified mapping, R8) ----
__device__ __forceinline__ void mma_tf32(float* d, const uint32_t* a, const uint32_t* b) {
    asm volatile(
        "mma.sync.aligned.m16n8k8.row.col.f32.tf32.tf32.f32 "
        "{%0,%1,%2,%3}, {%4,%5,%6,%7}, {%8,%9}, {%0,%1,%2,%3};"
        : "+f"(d[0]), "+f"(d[1]), "+f"(d[2]), "+f"(d[3])
        : "r"(a[0]), "r"(a[1]), "r"(a[2]), "r"(a[3]), "r"(b[0]), "r"(b[1]));
}

// ---- K0 ----
__global__ void k_zero() {
    int i = blockIdx.x*256 + threadIdx.x;
    if (i < B_*N_) g_colsum[i] = 0.f;
}

// ---- K1: QKV = X @ W^T + b via tf32 mma. grid (768, 3); warp = 16 rows x 128 cols ----
__global__ __launch_bounds__(256,1) void k_qkv_mma(const float* __restrict__ X,
                                                   const float* __restrict__ W,
                                                   const float* __restrict__ bias) {
    extern __shared__ float sm[];
    float* Xs = sm;                 // [128][132]
    float* Ws = sm + 128*132;       // [128][132]
    const int tid = threadIdx.x, w = tid>>5, lane = tid&31;
    const int g = lane>>2, tg = lane&3;
    const size_t rb = (size_t)blockIdx.x * 128;
    const int cb = blockIdx.y * 128;

    // stage W rows cb..cb+127 (block-wide)
    #pragma unroll
    for (int jj = 0; jj < 16; jj++) {
        int idx = tid + jj*256, r = idx>>5, f4 = idx&31;
        *reinterpret_cast<float4*>(&Ws[r*132 + f4*4]) =
            reinterpret_cast<const float4*>(W)[(size_t)(cb + r)*32 + f4];
    }
    // stage this warp's 16 X rows (warp-private region)
    #pragma unroll
    for (int jj = 0; jj < 2; jj++) {
        int idx = lane + jj*32, r = w*16 + (idx>>2)*2 + (idx&1)*1; // cover 16 rows x 32 f4 / 32 lanes
        (void)r;
    }
    #pragma unroll
    for (int it = 0; it < 16; it++) {       // 16 rows x 32 float4 = 512 / 32 lanes
        int idx = lane + it*32, r = idx>>5, f4 = idx&31;
        *reinterpret_cast<float4*>(&Xs[(w*16 + r)*132 + f4*4]) =
            reinterpret_cast<const float4*>(X)[(rb + w*16 + r)*32 + f4];
    }
    __syncthreads();

    const uint32_t* Xu = reinterpret_cast<const uint32_t*>(Xs);
    const uint32_t* Wu = reinterpret_cast<const uint32_t*>(Ws);
    float D[16][4];
    #pragma unroll
    for (int nt=0;nt<16;nt++) { D[nt][0]=0.f; D[nt][1]=0.f; D[nt][2]=0.f; D[nt][3]=0.f; }
    #pragma unroll
    for (int s = 0; s < 16; s++) {
        uint32_t a[4];
        int ar = (w*16+g)*132 + 8*s + tg;
        a[0] = Xu[ar];     a[1] = Xu[ar + 8*132];
        a[2] = Xu[ar + 4]; a[3] = Xu[ar + 8*132 + 4];
        #pragma unroll
        for (int nt = 0; nt < 16; nt++) {
            int br = (nt*8+g)*132 + 8*s + tg;
            uint32_t b[2] = { Wu[br], Wu[br+4] };
            mma_tf32(D[nt], a, b);
        }
    }

    float* dst = (blockIdx.y == 0) ? g_Q : (blockIdx.y == 1 ? g_K : g_V);
    #pragma unroll
    for (int nt = 0; nt < 16; nt++) {
        int col = nt*8 + 2*tg;
        float2 bb = *reinterpret_cast<const float2*>(&bias[cb + col]);
        size_t r0 = rb + w*16 + g;
        *reinterpret_cast<float2*>(&dst[r0*F_ + col]) =
            make_float2(D[nt][0] + bb.x, D[nt][1] + bb.y);
        *reinterpret_cast<float2*>(&dst[(r0+8)*F_ + col]) =
            make_float2(D[nt][2] + bb.x, D[nt][3] + bb.y);
    }
}

// ---- K2: softmax column sums, t = T-1 only (scalar fp32) ----
__global__ __launch_bounds__(256) void k_colsum() {
    extern __shared__ float sm[];
    float* Ss = sm;
    float* Qs = sm + 16*1024;
    float* Ks = Qs + 16*LDP;
    const int b = blockIdx.y, h = b*T_ + (T_-1);
    const int rb = blockIdx.x*16, tid = threadIdx.x;
    const float* Qh = g_Q + (size_t)h*N_*F_;
    const float* Kh = g_K + (size_t)h*N_*F_;
    #pragma unroll
    for (int j = 0; j < 2; j++) {
        int idx = tid + j*256, r = idx>>5, f4 = idx&31;
        *reinterpret_cast<float4*>(&Qs[r*LDP+f4*4]) =
            reinterpret_cast<const float4*>(Qh)[(size_t)(rb+r)*32+f4];
    }
    const int r = tid>>4, cg = tid&15;
    const float scale = 0.08838834764831845f;
    for (int kt = 0; kt < 16; kt++) {
        __syncthreads();
        #pragma unroll
        for (int j = 0; j < 8; j++) {
            int idx = tid + j*256, rr = idx>>5, f4 = idx&31;
            *reinterpret_cast<float4*>(&Ks[rr*LDP+f4*4]) =
                reinterpret_cast<const float4*>(Kh)[(size_t)(kt*64+rr)*32+f4];
        }
        __syncthreads();
        float acc[4] = {0.f,0.f,0.f,0.f};
        for (int k = 0; k < 128; k++) {
            float q = Qs[r*LDP+k];
            #pragma unroll
            for (int jj=0;jj<4;jj++) acc[jj] += q*Ks[(jj*16+cg)*LDP+k];
        }
        #pragma unroll
        for (int jj=0;jj<4;jj++) Ss[r*1024 + kt*64 + jj*16 + cg] = acc[jj]*scale;
    }
    __syncthreads();
    float m = -FLT_MAX;
    for (int s = 0; s < 64; s++) m = fmaxf(m, Ss[r*1024 + s*16 + cg]);
    #pragma unroll
    for (int o=8;o>0;o>>=1) m = fmaxf(m, __shfl_xor_sync(0xffffffffu, m, o));
    float l = 0.f;
    for (int s = 0; s < 64; s++) {
        float p = __expf(Ss[r*1024 + s*16 + cg] - m);
        Ss[r*1024 + s*16 + cg] = p; l += p;
    }
    #pragma unroll
    for (int o=8;o>0;o>>=1) l += __shfl_xor_sync(0xffffffffu, l, o);
    float inv = 1.f/l;
    for (int s = 0; s < 64; s++) Ss[r*1024 + s*16 + cg] *= inv;
    __syncthreads();
    #pragma unroll
    for (int j = 0; j < 4; j++) {
        int c = tid + j*256;
        float ssum = 0.f;
        #pragma unroll
        for (int rr=0;rr<16;rr++) ssum += Ss[rr*1024 + c];
        atomicAdd(&g_colsum[b*N_ + c], ssum);
    }
}

// ---- K3 ----
__global__ void k_ylast() {
    __shared__ float vals[N_]; __shared__ float rv[256];
    __shared__ int ri[256]; __shared__ int excl[3];
    const int b = blockIdx.x, tid = threadIdx.x;
    #pragma unroll
    for (int j=0;j<4;j++) vals[tid+j*256] = g_colsum[b*N_ + tid + j*256];
    __syncthreads();
    for (int round = 0; round < 3; round++) {
        float bv = FLT_MAX; int bi = N_;
        #pragma unroll
        for (int j=0;j<4;j++) {
            int i = tid + j*256; bool skip = false;
            for (int e=0;e<round;e++) if (excl[e]==i) skip = true;
            if (!skip) { float v = vals[i];
                if (v < bv || (v==bv && i<bi)) { bv=v; bi=i; } }
        }
        rv[tid]=bv; ri[tid]=bi; __syncthreads();
        for (int st=128; st>0; st>>=1) {
            if (tid < st) {
                float v2=rv[tid+st]; int i2=ri[tid+st];
                if (v2<rv[tid] || (v2==rv[tid] && i2<ri[tid])) { rv[tid]=v2; ri[tid]=i2; }
            }
            __syncthreads();
        }
        if (tid==0) excl[round] = ri[0];
        __syncthreads();
    }
    if (tid==0) g_ylast[b] = excl[2];
}

// ---- K4 ----
__global__ void k_mixup() {
    const int b = blockIdx.x / FRONT_T_, t = blockIdx.x % FRONT_T_, f = threadIdx.x;
    const int y = g_ylast[b];
    const int ys = max(y-1,0), ye = min(y+2,N_);
    float s = 0.f;
    for (int n = ys; n < ye; n++) s += g_V[(((size_t)(b*T_+t))*N_+n)*F_+f];
    float m = s/(float)(ye-ys);
    g_V[(((size_t)(b*T_+t))*N_+y)*F_+f] = fminf(fmaxf(truncf(m),0.f),255.f);
}

// ---- K5: flash attention via mma.sync tf32 (unchanged; passed R8) ----
__global__ __launch_bounds__(256,2) void k_attn_mma() {
    extern __shared__ float sm[];
    float* Qs = sm;
    float* Ks = sm + 64*132;
    float* Vs = sm + 2*64*132;
    float* sl = sm + 3*64*132;
    float* Ps = Ks;
    const int h = blockIdx.y, qb = blockIdx.x*64;
    const float* Qh = g_Q + (size_t)h*N_*F_;
    const float* Kh = g_K + (size_t)h*N_*F_;
    const float* Vh = g_V + (size_t)h*N_*F_;
    float* Oh = g_AO + (size_t)h*N_*F_;
    const int tid = threadIdx.x, w = tid>>5, lane = tid&31;
    const int wm = w>>1, wn = w&1, g = lane>>2, tg = lane&3;

    #pragma unroll
    for (int jj=0;jj<8;jj++) {
        int idx = tid + jj*256, r = idx>>5, f4 = idx&31;
        *reinterpret_cast<float4*>(&Qs[r*132 + f4*4]) =
            reinterpret_cast<const float4*>(Qh)[(size_t)(qb+r)*32 + f4];
    }
    if (tid < 64) sl[tid] = 0.f;

    float O[8][4];
    #pragma unroll
    for (int nt=0;nt<8;nt++) { O[nt][0]=0.f; O[nt][1]=0.f; O[nt][2]=0.f; O[nt][3]=0.f; }
    float l0 = 0.f, l1 = 0.f;
    const float scale = 0.08838834764831845f;

    const uint32_t* Qu = reinterpret_cast<const uint32_t*>(Qs);
    const uint32_t* Ku = reinterpret_cast<const uint32_t*>(Ks);
    const uint32_t* Vu = reinterpret_cast<const uint32_t*>(Vs);
    const uint32_t* Pu = reinterpret_cast<const uint32_t*>(Ps);

    for (int kt = 0; kt < 16; kt++) {
        __syncthreads();
        #pragma unroll
        for (int jj=0;jj<8;jj++) {
            int idx = tid + jj*256, r = idx>>5, f4 = idx&31;
            *reinterpret_cast<float4*>(&Ks[r*132 + f4*4]) =
                reinterpret_cast<const float4*>(Kh)[(size_t)(kt*64+r)*32 + f4];
            *reinterpret_cast<float4*>(&Vs[r*132 + f4*4]) =
                reinterpret_cast<const float4*>(Vh)[(size_t)(kt*64+r)*32 + f4];
        }
        __syncthreads();

        float S[4][4];
        #pragma unroll
        for (int nt=0;nt<4;nt++) { S[nt][0]=0.f; S[nt][1]=0.f; S[nt][2]=0.f; S[nt][3]=0.f; }
        #pragma unroll
        for (int s=0;s<16;s++) {
            uint32_t a[4];
            int ar = (wm*16+g)*132 + 8*s + tg;
            a[0] = Qu[ar];       a[1] = Qu[ar + 8*132];
            a[2] = Qu[ar + 4];   a[3] = Qu[ar + 8*132 + 4];
            #pragma unroll
            for (int nt=0;nt<4;nt++) {
                int br = (wn*32+nt*8+g)*132 + 8*s + tg;
                uint32_t b[2] = { Ku[br], Ku[br+4] };
                mma_tf32(S[nt], a, b);
            }
        }
        __syncthreads();

        #pragma unroll
        for (int nt=0;nt<4;nt++) {
            float e0 = __expf(S[nt][0]*scale), e1 = __expf(S[nt][1]*scale);
            float e2 = __expf(S[nt][2]*scale), e3 = __expf(S[nt][3]*scale);
            l0 += e0+e1; l1 += e2+e3;
            int pr = (wm*16+g)*68 + wn*32 + nt*8 + 2*tg;
            *reinterpret_cast<float2*>(&Ps[pr])        = make_float2(e0,e1);
            *reinterpret_cast<float2*>(&Ps[pr + 8*68]) = make_float2(e2,e3);
        }
        __syncthreads();

        #pragma unroll
        for (int s=0;s<8;s++) {
            uint32_t a[4];
            int ar = (wm*16+g)*68 + 8*s + tg;
            a[0] = Pu[ar];       a[1] = Pu[ar + 8*68];
            a[2] = Pu[ar + 4];   a[3] = Pu[ar + 8*68 + 4];
            #pragma unroll
            for (int nt=0;nt<8;nt++) {
                int br = (8*s+tg)*132 + wn*64 + nt*8 + g;
                uint32_t b[2] = { Vu[br], Vu[br + 4*132] };
                mma_tf32(O[nt], a, b);
            }
        }
    }

    l0 += __shfl_xor_sync(0xffffffffu, l0, 1);
    l0 += __shfl_xor_sync(0xffffffffu, l0, 2);
    l1 += __shfl_xor_sync(0xffffffffu, l1, 1);
    l1 += __shfl_xor_sync(0xffffffffu, l1, 2);
    if (tg == 0) {
        atomicAdd(&sl[wm*16+g],   l0);
        atomicAdd(&sl[wm*16+g+8], l1);
    }
    __syncthreads();
    float inv0 = 1.f/sl[wm*16+g], inv1 = 1.f/sl[wm*16+g+8];
    #pragma unroll
    for (int nt=0;nt<8;nt++) {
        size_t r0 = (size_t)(qb+wm*16+g)*F_ + wn*64 + nt*8 + 2*tg;
        *reinterpret_cast<float2*>(&Oh[r0])        = make_float2(O[nt][0]*inv0, O[nt][1]*inv0);
        *reinterpret_cast<float2*>(&Oh[r0 + 8*F_]) = make_float2(O[nt][2]*inv1, O[nt][3]*inv1);
    }
}

// ---- K6: fused FF1+GELU+FF2+residual+LN via tf32 mma ----
// Each warp owns rows 16w..16w+15 of the tile: after W staging, warp-local only.
__global__ __launch_bounds__(256,1) void k_ffln_mma(const float* __restrict__ Xin,
        const float* __restrict__ W1, const float* __restrict__ b1,
        const float* __restrict__ W2, const float* __restrict__ b2,
        const float* __restrict__ lg, const float* __restrict__ lb,
        float* __restrict__ out) {
    extern __shared__ float sm[];
    float* Xs  = sm;                 // [128][132] — X, then H in place
    float* W1s = sm + 128*132;
    float* W2s = sm + 2*128*132;
    const int tid = threadIdx.x, w = tid>>5, lane = tid&31;
    const int g = lane>>2, tg = lane&3;
    const size_t rb = (size_t)blockIdx.x * 128;

    #pragma unroll
    for (int jj = 0; jj < 16; jj++) {
        int idx = tid + jj*256, r = idx>>5, f4 = idx&31;
        *reinterpret_cast<float4*>(&W1s[r*132 + f4*4]) =
            reinterpret_cast<const float4*>(W1)[(size_t)r*32 + f4];
        *reinterpret_cast<float4*>(&W2s[r*132 + f4*4]) =
            reinterpret_cast<const float4*>(W2)[(size_t)r*32 + f4];
    }
    #pragma unroll
    for (int it = 0; it < 16; it++) {
        int idx = lane + it*32, r = idx>>5, f4 = idx&31;
        *reinterpret_cast<float4*>(&Xs[(w*16 + r)*132 + f4*4]) =
            reinterpret_cast<const float4*>(g_AO)[(rb + w*16 + r)*32 + f4];
    }
    __syncthreads();

    const uint32_t* Xu = reinterpret_cast<const uint32_t*>(Xs);
    const uint32_t* W1u = reinterpret_cast<const uint32_t*>(W1s);
    const uint32_t* W2u = reinterpret_cast<const uint32_t*>(W2s);
    const float is2 = 0.7071067811865475f;

    float D[16][4];
    #pragma unroll
    for (int nt=0;nt<16;nt++) { D[nt][0]=0.f; D[nt][1]=0.f; D[nt][2]=0.f; D[nt][3]=0.f; }
    #pragma unroll
    for (int s = 0; s < 16; s++) {
        uint32_t a[4];
        int ar = (w*16+g)*132 + 8*s + tg;
        a[0] = Xu[ar];     a[1] = Xu[ar + 8*132];
        a[2] = Xu[ar + 4]; a[3] = Xu[ar + 8*132 + 4];
        #pragma unroll
        for (int nt = 0; nt < 16; nt++) {
            int br = (nt*8+g)*132 + 8*s + tg;
            uint32_t b[2] = { W1u[br], W1u[br+4] };
            mma_tf32(D[nt], a, b);
        }
    }
    // gelu(D + b1) -> store H back into this warp's Xs rows
    #pragma unroll
    for (int nt = 0; nt < 16; nt++) {
        int col = nt*8 + 2*tg;
        float2 bb = *reinterpret_cast<const float2*>(&b1[col]);
        float h0 = D[nt][0]+bb.x, h1 = D[nt][1]+bb.y;
        float h2 = D[nt][2]+bb.x, h3 = D[nt][3]+bb.y;
        h0 = 0.5f*h0*(1.f+erff(h0*is2)); h1 = 0.5f*h1*(1.f+erff(h1*is2));
        h2 = 0.5f*h2*(1.f+erff(h2*is2)); h3 = 0.5f*h3*(1.f+erff(h3*is2));
        *reinterpret_cast<float2*>(&Xs[(w*16+g)*132 + col])   = make_float2(h0,h1);
        *reinterpret_cast<float2*>(&Xs[(w*16+g+8)*132 + col]) = make_float2(h2,h3);
    }
    __syncwarp();

    #pragma unroll
    for (int nt=0;nt<16;nt++) { D[nt][0]=0.f; D[nt][1]=0.f; D[nt][2]=0.f; D[nt][3]=0.f; }
    #pragma unroll
    for (int s = 0; s < 16; s++) {
        uint32_t a[4];
        int ar = (w*16+g)*132 + 8*s + tg;
        a[0] = Xu[ar];     a[1] = Xu[ar + 8*132];
        a[2] = Xu[ar + 4]; a[3] = Xu[ar + 8*132 + 4];
        #pragma unroll
        for (int nt = 0; nt < 16; nt++) {
            int br = (nt*8+g)*132 + 8*s + tg;
            uint32_t b[2] = { W2u[br], W2u[br+4] };
            mma_tf32(D[nt], a, b);
        }
    }
    // residual + bias, then LN over the two owned rows
    size_t r0 = rb + w*16 + g, r1 = r0 + 8;
    float s0 = 0.f, q0 = 0.f, s1 = 0.f, q1 = 0.f;
    #pragma unroll
    for (int nt = 0; nt < 16; nt++) {
        int col = nt*8 + 2*tg;
        float2 bb = *reinterpret_cast<const float2*>(&b2[col]);
        float2 i0 = *reinterpret_cast<const float2*>(&Xin[r0*F_ + col]);
        float2 i1 = *reinterpret_cast<const float2*>(&Xin[r1*F_ + col]);
        D[nt][0] += bb.x + i0.x; D[nt][1] += bb.y + i0.y;
        D[nt][2] += bb.x + i1.x; D[nt][3] += bb.y + i1.y;
        s0 += D[nt][0] + D[nt][1]; q0 += D[nt][0]*D[nt][0] + D[nt][1]*D[nt][1];
        s1 += D[nt][2] + D[nt][3]; q1 += D[nt][2]*D[nt][2] + D[nt][3]*D[nt][3];
    }
    s0 += __shfl_xor_sync(0xffffffffu, s0, 1); s0 += __shfl_xor_sync(0xffffffffu, s0, 2);
    q0 += __shfl_xor_sync(0xffffffffu, q0, 1); q0 += __shfl_xor_sync(0xffffffffu, q0, 2);
    s1 += __shfl_xor_sync(0xffffffffu, s1, 1); s1 += __shfl_xor_sync(0xffffffffu, s1, 2);
    q1 += __shfl_xor_sync(0xffffffffu, q1, 1); q1 += __shfl_xor_sync(0xffffffffu, q1, 2);
    float mu0 = s0*(1.f/128.f), mu1 = s1*(1.f/128.f);
    float rs0 = rsqrtf(fmaxf(q0*(1.f/128.f) - mu0*mu0, 0.f) + EPS_);
    float rs1 = rsqrtf(fmaxf(q1*(1.f/128.f) - mu1*mu1, 0.f) + EPS_);
    #pragma unroll
    for (int nt = 0; nt < 16; nt++) {
        int col = nt*8 + 2*tg;
        float2 gg = *reinterpret_cast<const float2*>(&lg[col]);
        float2 bb = *reinterpret_cast<const float2*>(&lb[col]);
        *reinterpret_cast<float2*>(&out[r0*F_ + col]) = make_float2(
            (D[nt][0]-mu0)*rs0*gg.x + bb.x, (D[nt][1]-mu0)*rs0*gg.y + bb.y);
        *reinterpret_cast<float2*>(&out[r1*F_ + col]) = make_float2(
            (D[nt][2]-mu1)*rs1*gg.x + bb.x, (D[nt][3]-mu1)*rs1*gg.y + bb.y);
    }
}

extern "C" void kernel_launch(void* const* d_in, const int* in_sizes, int n_in,
                              void* d_out, int out_size) {
    const float* input = (const float*)d_in[0];
    const float* W_xff = (const float*)d_in[1];
    const float* b_xff = (const float*)d_in[2];
    const float* W_ff1 = (const float*)d_in[3];
    const float* b_ff1 = (const float*)d_in[4];
    const float* W_ff2 = (const float*)d_in[5];
    const float* b_ff2 = (const float*)d_in[6];
    const float* ln_g  = (const float*)d_in[7];
    const float* ln_b  = (const float*)d_in[8];
    float* out = (float*)d_out;

    const int smQKV = 2*128*132*4;                    // 135168
    const int smCOL = (16*1024 + 16*LDP + 64*LDP)*4;  // 107776
    const int smATT = (3*64*132 + 64)*4;              // 101632
    const int smFF  = 3*128*132*4;                    // 202752
    cudaFuncSetAttribute(k_qkv_mma,  cudaFuncAttributeMaxDynamicSharedMemorySize, smQKV);
    cudaFuncSetAttribute(k_colsum,   cudaFuncAttributeMaxDynamicSharedMemorySize, smCOL);
    cudaFuncSetAttribute(k_attn_mma, cudaFuncAttributeMaxDynamicSharedMemorySize, smATT);
    cudaFuncSetAttribute(k_ffln_mma, cudaFuncAttributeMaxDynamicSharedMemorySize, smFF);

    k_zero<<<16, 256>>>();
    k_qkv_mma<<<dim3(ROWS_TOT/128, 3), 256, smQKV>>>(input, W_xff, b_xff);
    k_colsum<<<dim3(N_/16, B_), 256, smCOL>>>();
    k_ylast<<<B_, 256>>>();
    k_mixup<<<B_*FRONT_T_, F_>>>();
    k_attn_mma<<<dim3(N_/64, H_), 256, smATT>>>();
    k_ffln_mma<<<ROWS_TOT/128, 256, smFF>>>(input, W_ff1, b_ff1, W_ff2, b_ff2,
                                            ln_g, ln_b, out);
}

// round 14
// speedup vs baseline: 1.0016x; 1.0016x over previous
#include <cuda_runtime.h>
#include <math.h>
#include <float.h>
#include <stdint.h>

#define B_ 4
#define T_ 24
#define N_ 1024
#define F_ 128
#define H_ (B_*T_)
#define FRONT_T_ 12
#define ROWS_TOT (H_*N_)
#define LDP 132
#define EPS_ 1e-5f

__device__ __align__(128) float g_Q[(size_t)H_*N_*F_];
__device__ __align__(128) float g_K[(size_t)H_*N_*F_];
__device__ __align__(128) float g_V[(size_t)H_*N_*F_];
__device__ __align__(128) float g_AO[(size_t)H_*N_*F_];
__device__ float g_colsum[B_*N_];
__device__ int g_ylast[B_];

// ---- mma.sync m16n8k8 tf32 (verified mapping, R8) ----
__device__ __forceinline__ void mma_tf32(float* d, const uint32_t* a, const uint32_t* b) {
    asm volatile(
        "mma.sync.aligned.m16n8k8.row.col.f32.tf32.tf32.f32 "
        "{%0,%1,%2,%3}, {%4,%5,%6,%7}, {%8,%9}, {%0,%1,%2,%3};"
        : "+f"(d[0]), "+f"(d[1]), "+f"(d[2]), "+f"(d[3])
        : "r"(a[0]), "r"(a[1]), "r"(a[2]), "r"(a[3]), "r"(b[0]), "r"(b[1]));
}

// ---- K0 ----
__global__ void k_zero() {
    int i = blockIdx.x*256 + threadIdx.x;
    if (i < B_*N_) g_colsum[i] = 0.f;
}

// ---- K1: QKV = X @ W^T + b via tf32 mma. grid (768, 3); warp = 16 rows x 128 cols ----
__global__ __launch_bounds__(256,1) void k_qkv_mma(const float* __restrict__ X,
                                                   const float* __restrict__ W,
                                                   const float* __restrict__ bias) {
    extern __shared__ float sm[];
    float* Xs = sm;                 // [128][132]
    float* Ws = sm + 128*132;       // [128][132]
    const int tid = threadIdx.x, w = tid>>5, lane = tid&31;
    const int g = lane>>2, tg = lane&3;
    const size_t rb = (size_t)blockIdx.x * 128;
    const int cb = blockIdx.y * 128;

    // stage W rows cb..cb+127 (block-wide)
    #pragma unroll
    for (int jj = 0; jj < 16; jj++) {
        int idx = tid + jj*256, r = idx>>5, f4 = idx&31;
        *reinterpret_cast<float4*>(&Ws[r*132 + f4*4]) =
            reinterpret_cast<const float4*>(W)[(size_t)(cb + r)*32 + f4];
    }
    // stage this warp's 16 X rows (warp-private region)
    #pragma unroll
    for (int jj = 0; jj < 2; jj++) {
        int idx = lane + jj*32, r = w*16 + (idx>>2)*2 + (idx&1)*1; // cover 16 rows x 32 f4 / 32 lanes
        (void)r;
    }
    #pragma unroll
    for (int it = 0; it < 16; it++) {       // 16 rows x 32 float4 = 512 / 32 lanes
        int idx = lane + it*32, r = idx>>5, f4 = idx&31;
        *reinterpret_cast<float4*>(&Xs[(w*16 + r)*132 + f4*4]) =
            reinterpret_cast<const float4*>(X)[(rb + w*16 + r)*32 + f4];
    }
    __syncthreads();

    const uint32_t* Xu = reinterpret_cast<const uint32_t*>(Xs);
    const uint32_t* Wu = reinterpret_cast<const uint32_t*>(Ws);
    float D[16][4];
    #pragma unroll
    for (int nt=0;nt<16;nt++) { D[nt][0]=0.f; D[nt][1]=0.f; D[nt][2]=0.f; D[nt][3]=0.f; }
    #pragma unroll
    for (int s = 0; s < 16; s++) {
        uint32_t a[4];
        int ar = (w*16+g)*132 + 8*s + tg;
        a[0] = Xu[ar];     a[1] = Xu[ar + 8*132];
        a[2] = Xu[ar + 4]; a[3] = Xu[ar + 8*132 + 4];
        #pragma unroll
        for (int nt = 0; nt < 16; nt++) {
            int br = (nt*8+g)*132 + 8*s + tg;
            uint32_t b[2] = { Wu[br], Wu[br+4] };
            mma_tf32(D[nt], a, b);
        }
    }

    float* dst = (blockIdx.y == 0) ? g_Q : (blockIdx.y == 1 ? g_K : g_V);
    #pragma unroll
    for (int nt = 0; nt < 16; nt++) {
        int col = nt*8 + 2*tg;
        float2 bb = *reinterpret_cast<const float2*>(&bias[cb + col]);
        size_t r0 = rb + w*16 + g;
        *reinterpret_cast<float2*>(&dst[r0*F_ + col]) =
            make_float2(D[nt][0] + bb.x, D[nt][1] + bb.y);
        *reinterpret_cast<float2*>(&dst[(r0+8)*F_ + col]) =
            make_float2(D[nt][2] + bb.x, D[nt][3] + bb.y);
    }
}

// ---- K2: softmax column sums, t = T-1 only (scalar fp32) ----
__global__ __launch_bounds__(256) void k_colsum() {
    extern __shared__ float sm[];
    float* Ss = sm;
    float* Qs = sm + 16*1024;
    float* Ks = Qs + 16*LDP;
    const int b = blockIdx.y, h = b*T_ + (T_-1);
    const int rb = blockIdx.x*16, tid = threadIdx.x;
    const float* Qh = g_Q + (size_t)h*N_*F_;
    const float* Kh = g_K + (size_t)h*N_*F_;
    #pragma unroll
    for (int j = 0; j < 2; j++) {
        int idx = tid + j*256, r = idx>>5, f4 = idx&31;
        *reinterpret_cast<float4*>(&Qs[r*LDP+f4*4]) =
            reinterpret_cast<const float4*>(Qh)[(size_t)(rb+r)*32+f4];
    }
    const int r = tid>>4, cg = tid&15;
    const float scale = 0.08838834764831845f;
    for (int kt = 0; kt < 16; kt++) {
        __syncthreads();
        #pragma unroll
        for (int j = 0; j < 8; j++) {
            int idx = tid + j*256, rr = idx>>5, f4 = idx&31;
            *reinterpret_cast<float4*>(&Ks[rr*LDP+f4*4]) =
                reinterpret_cast<const float4*>(Kh)[(size_t)(kt*64+rr)*32+f4];
        }
        __syncthreads();
        float acc[4] = {0.f,0.f,0.f,0.f};
        for (int k = 0; k < 128; k++) {
            float q = Qs[r*LDP+k];
            #pragma unroll
            for (int jj=0;jj<4;jj++) acc[jj] += q*Ks[(jj*16+cg)*LDP+k];
        }
        #pragma unroll
        for (int jj=0;jj<4;jj++) Ss[r*1024 + kt*64 + jj*16 + cg] = acc[jj]*scale;
    }
    __syncthreads();
    float m = -FLT_MAX;
    for (int s = 0; s < 64; s++) m = fmaxf(m, Ss[r*1024 + s*16 + cg]);
    #pragma unroll
    for (int o=8;o>0;o>>=1) m = fmaxf(m, __shfl_xor_sync(0xffffffffu, m, o));
    float l = 0.f;
    for (int s = 0; s < 64; s++) {
        float p = __expf(Ss[r*1024 + s*16 + cg] - m);
        Ss[r*1024 + s*16 + cg] = p; l += p;
    }
    #pragma unroll
    for (int o=8;o>0;o>>=1) l += __shfl_xor_sync(0xffffffffu, l, o);
    float inv = 1.f/l;
    for (int s = 0; s < 64; s++) Ss[r*1024 + s*16 + cg] *= inv;
    __syncthreads();
    #pragma unroll
    for (int j = 0; j < 4; j++) {
        int c = tid + j*256;
        float ssum = 0.f;
        #pragma unroll
        for (int rr=0;rr<16;rr++) ssum += Ss[rr*1024 + c];
        atomicAdd(&g_colsum[b*N_ + c], ssum);
    }
}

// ---- K3 ----
__global__ void k_ylast() {
    __shared__ float vals[N_]; __shared__ float rv[256];
    __shared__ int ri[256]; __shared__ int excl[3];
    const int b = blockIdx.x, tid = threadIdx.x;
    #pragma unroll
    for (int j=0;j<4;j++) vals[tid+j*256] = g_colsum[b*N_ + tid + j*256];
    __syncthreads();
    for (int round = 0; round < 3; round++) {
        float bv = FLT_MAX; int bi = N_;
        #pragma unroll
        for (int j=0;j<4;j++) {
            int i = tid + j*256; bool skip = false;
            for (int e=0;e<round;e++) if (excl[e]==i) skip = true;
            if (!skip) { float v = vals[i];
                if (v < bv || (v==bv && i<bi)) { bv=v; bi=i; } }
        }
        rv[tid]=bv; ri[tid]=bi; __syncthreads();
        for (int st=128; st>0; st>>=1) {
            if (tid < st) {
                float v2=rv[tid+st]; int i2=ri[tid+st];
                if (v2<rv[tid] || (v2==rv[tid] && i2<ri[tid])) { rv[tid]=v2; ri[tid]=i2; }
            }
            __syncthreads();
        }
        if (tid==0) excl[round] = ri[0];
        __syncthreads();
    }
    if (tid==0) g_ylast[b] = excl[2];
}

// ---- K4 ----
__global__ void k_mixup() {
    const int b = blockIdx.x / FRONT_T_, t = blockIdx.x % FRONT_T_, f = threadIdx.x;
    const int y = g_ylast[b];
    const int ys = max(y-1,0), ye = min(y+2,N_);
    float s = 0.f;
    for (int n = ys; n < ye; n++) s += g_V[(((size_t)(b*T_+t))*N_+n)*F_+f];
    float m = s/(float)(ye-ys);
    g_V[(((size_t)(b*T_+t))*N_+y)*F_+f] = fminf(fmaxf(truncf(m),0.f),255.f);
}

// ---- K5: flash attention via mma.sync tf32 (unchanged; passed R8) ----
__global__ __launch_bounds__(256,2) void k_attn_mma() {
    extern __shared__ float sm[];
    float* Qs = sm;
    float* Ks = sm + 64*132;
    float* Vs = sm + 2*64*132;
    float* sl = sm + 3*64*132;
    float* Ps = Ks;
    const int h = blockIdx.y, qb = blockIdx.x*64;
    const float* Qh = g_Q + (size_t)h*N_*F_;
    const float* Kh = g_K + (size_t)h*N_*F_;
    const float* Vh = g_V + (size_t)h*N_*F_;
    float* Oh = g_AO + (size_t)h*N_*F_;
    const int tid = threadIdx.x, w = tid>>5, lane = tid&31;
    const int wm = w>>1, wn = w&1, g = lane>>2, tg = lane&3;

    #pragma unroll
    for (int jj=0;jj<8;jj++) {
        int idx = tid + jj*256, r = idx>>5, f4 = idx&31;
        *reinterpret_cast<float4*>(&Qs[r*132 + f4*4]) =
            reinterpret_cast<const float4*>(Qh)[(size_t)(qb+r)*32 + f4];
    }
    if (tid < 64) sl[tid] = 0.f;

    float O[8][4];
    #pragma unroll
    for (int nt=0;nt<8;nt++) { O[nt][0]=0.f; O[nt][1]=0.f; O[nt][2]=0.f; O[nt][3]=0.f; }
    float l0 = 0.f, l1 = 0.f;
    const float scale = 0.08838834764831845f;

    const uint32_t* Qu = reinterpret_cast<const uint32_t*>(Qs);
    const uint32_t* Ku = reinterpret_cast<const uint32_t*>(Ks);
    const uint32_t* Vu = reinterpret_cast<const uint32_t*>(Vs);
    const uint32_t* Pu = reinterpret_cast<const uint32_t*>(Ps);

    for (int kt = 0; kt < 16; kt++) {
        __syncthreads();
        #pragma unroll
        for (int jj=0;jj<8;jj++) {
            int idx = tid + jj*256, r = idx>>5, f4 = idx&31;
            *reinterpret_cast<float4*>(&Ks[r*132 + f4*4]) =
                reinterpret_cast<const float4*>(Kh)[(size_t)(kt*64+r)*32 + f4];
            *reinterpret_cast<float4*>(&Vs[r*132 + f4*4]) =
                reinterpret_cast<const float4*>(Vh)[(size_t)(kt*64+r)*32 + f4];
        }
        __syncthreads();

        float S[4][4];
        #pragma unroll
        for (int nt=0;nt<4;nt++) { S[nt][0]=0.f; S[nt][1]=0.f; S[nt][2]=0.f; S[nt][3]=0.f; }
        #pragma unroll
        for (int s=0;s<16;s++) {
            uint32_t a[4];
            int ar = (wm*16+g)*132 + 8*s + tg;
            a[0] = Qu[ar];       a[1] = Qu[ar + 8*132];
            a[2] = Qu[ar + 4];   a[3] = Qu[ar + 8*132 + 4];
            #pragma unroll
            for (int nt=0;nt<4;nt++) {
                int br = (wn*32+nt*8+g)*132 + 8*s + tg;
                uint32_t b[2] = { Ku[br], Ku[br+4] };
                mma_tf32(S[nt], a, b);
            }
        }
        __syncthreads();

        #pragma unroll
        for (int nt=0;nt<4;nt++) {
            float e0 = __expf(S[nt][0]*scale), e1 = __expf(S[nt][1]*scale);
            float e2 = __expf(S[nt][2]*scale), e3 = __expf(S[nt][3]*scale);
            l0 += e0+e1; l1 += e2+e3;
            int pr = (wm*16+g)*68 + wn*32 + nt*8 + 2*tg;
            *reinterpret_cast<float2*>(&Ps[pr])        = make_float2(e0,e1);
            *reinterpret_cast<float2*>(&Ps[pr + 8*68]) = make_float2(e2,e3);
        }
        __syncthreads();

        #pragma unroll
        for (int s=0;s<8;s++) {
            uint32_t a[4];
            int ar = (wm*16+g)*68 + 8*s + tg;
            a[0] = Pu[ar];       a[1] = Pu[ar + 8*68];
            a[2] = Pu[ar + 4];   a[3] = Pu[ar + 8*68 + 4];
            #pragma unroll
            for (int nt=0;nt<8;nt++) {
                int br = (8*s+tg)*132 + wn*64 + nt*8 + g;
                uint32_t b[2] = { Vu[br], Vu[br + 4*132] };
                mma_tf32(O[nt], a, b);
            }
        }
    }

    l0 += __shfl_xor_sync(0xffffffffu, l0, 1);
    l0 += __shfl_xor_sync(0xffffffffu, l0, 2);
    l1 += __shfl_xor_sync(0xffffffffu, l1, 1);
    l1 += __shfl_xor_sync(0xffffffffu, l1, 2);
    if (tg == 0) {
        atomicAdd(&sl[wm*16+g],   l0);
        atomicAdd(&sl[wm*16+g+8], l1);
    }
    __syncthreads();
    float inv0 = 1.f/sl[wm*16+g], inv1 = 1.f/sl[wm*16+g+8];
    #pragma unroll
    for (int nt=0;nt<8;nt++) {
        size_t r0 = (size_t)(qb+wm*16+g)*F_ + wn*64 + nt*8 + 2*tg;
        *reinterpret_cast<float2*>(&Oh[r0])        = make_float2(O[nt][0]*inv0, O[nt][1]*inv0);
        *reinterpret_cast<float2*>(&Oh[r0 + 8*F_]) = make_float2(O[nt][2]*inv1, O[nt][3]*inv1);
    }
}

// ---- K6: fused FF1+GELU+FF2+residual+LN via tf32 mma ----
// Each warp owns rows 16w..16w+15 of the tile: after W staging, warp-local only.
__global__ __launch_bounds__(256,1) void k_ffln_mma(const float* __restrict__ Xin,
        const float* __restrict__ W1, const float* __restrict__ b1,
        const float* __restrict__ W2, const float* __restrict__ b2,
        const float* __restrict__ lg, const float* __restrict__ lb,
        float* __restrict__ out) {
    extern __shared__ float sm[];
    float* Xs  = sm;                 // [128][132] — X, then H in place
    float* W1s = sm + 128*132;
    float* W2s = sm + 2*128*132;
    const int tid = threadIdx.x, w = tid>>5, lane = tid&31;
    const int g = lane>>2, tg = lane&3;
    const size_t rb = (size_t)blockIdx.x * 128;

    #pragma unroll
    for (int jj = 0; jj < 16; jj++) {
        int idx = tid + jj*256, r = idx>>5, f4 = idx&31;
        *reinterpret_cast<float4*>(&W1s[r*132 + f4*4]) =
            reinterpret_cast<const float4*>(W1)[(size_t)r*32 + f4];
        *reinterpret_cast<float4*>(&W2s[r*132 + f4*4]) =
            reinterpret_cast<const float4*>(W2)[(size_t)r*32 + f4];
    }
    #pragma unroll
    for (int it = 0; it < 16; it++) {
        int idx = lane + it*32, r = idx>>5, f4 = idx&31;
        *reinterpret_cast<float4*>(&Xs[(w*16 + r)*132 + f4*4]) =
            reinterpret_cast<const float4*>(g_AO)[(rb + w*16 + r)*32 + f4];
    }
    __syncthreads();

    const uint32_t* Xu = reinterpret_cast<const uint32_t*>(Xs);
    const uint32_t* W1u = reinterpret_cast<const uint32_t*>(W1s);
    const uint32_t* W2u = reinterpret_cast<const uint32_t*>(W2s);
    const float is2 = 0.7071067811865475f;

    float D[16][4];
    #pragma unroll
    for (int nt=0;nt<16;nt++) { D[nt][0]=0.f; D[nt][1]=0.f; D[nt][2]=0.f; D[nt][3]=0.f; }
    #pragma unroll
    for (int s = 0; s < 16; s++) {
        uint32_t a[4];
        int ar = (w*16+g)*132 + 8*s + tg;
        a[0] = Xu[ar];     a[1] = Xu[ar + 8*132];
        a[2] = Xu[ar + 4]; a[3] = Xu[ar + 8*132 + 4];
        #pragma unroll
        for (int nt = 0; nt < 16; nt++) {
            int br = (nt*8+g)*132 + 8*s + tg;
            uint32_t b[2] = { W1u[br], W1u[br+4] };
            mma_tf32(D[nt], a, b);
        }
    }
    // gelu(D + b1) -> store H back into this warp's Xs rows
    #pragma unroll
    for (int nt = 0; nt < 16; nt++) {
        int col = nt*8 + 2*tg;
        float2 bb = *reinterpret_cast<const float2*>(&b1[col]);
        float h0 = D[nt][0]+bb.x, h1 = D[nt][1]+bb.y;
        float h2 = D[nt][2]+bb.x, h3 = D[nt][3]+bb.y;
        h0 = 0.5f*h0*(1.f+erff(h0*is2)); h1 = 0.5f*h1*(1.f+erff(h1*is2));
        h2 = 0.5f*h2*(1.f+erff(h2*is2)); h3 = 0.5f*h3*(1.f+erff(h3*is2));
        *reinterpret_cast<float2*>(&Xs[(w*16+g)*132 + col])   = make_float2(h0,h1);
        *reinterpret_cast<float2*>(&Xs[(w*16+g+8)*132 + col]) = make_float2(h2,h3);
    }
    __syncwarp();

    #pragma unroll
    for (int nt=0;nt<16;nt++) { D[nt][0]=0.f; D[nt][1]=0.f; D[nt][2]=0.f; D[nt][3]=0.f; }
    #pragma unroll
    for (int s = 0; s < 16; s++) {
        uint32_t a[4];
        int ar = (w*16+g)*132 + 8*s + tg;
        a[0] = Xu[ar];     a[1] = Xu[ar + 8*132];
        a[2] = Xu[ar + 4]; a[3] = Xu[ar + 8*132 + 4];
        #pragma unroll
        for (int nt = 0; nt < 16; nt++) {
            int br = (nt*8+g)*132 + 8*s + tg;
            uint32_t b[2] = { W2u[br], W2u[br+4] };
            mma_tf32(D[nt], a, b);
        }
    }
    // residual + bias, then LN over the two owned rows
    size_t r0 = rb + w*16 + g, r1 = r0 + 8;
    float s0 = 0.f, q0 = 0.f, s1 = 0.f, q1 = 0.f;
    #pragma unroll
    for (int nt = 0; nt < 16; nt++) {
        int col = nt*8 + 2*tg;
        float2 bb = *reinterpret_cast<const float2*>(&b2[col]);
        float2 i0 = *reinterpret_cast<const float2*>(&Xin[r0*F_ + col]);
        float2 i1 = *reinterpret_cast<const float2*>(&Xin[r1*F_ + col]);
        D[nt][0] += bb.x + i0.x; D[nt][1] += bb.y + i0.y;
        D[nt][2] += bb.x + i1.x; D[nt][3] += bb.y + i1.y;
        s0 += D[nt][0] + D[nt][1]; q0 += D[nt][0]*D[nt][0] + D[nt][1]*D[nt][1];
        s1 += D[nt][2] + D[nt][3]; q1 += D[nt][2]*D[nt][2] + D[nt][3]*D[nt][3];
    }
    s0 += __shfl_xor_sync(0xffffffffu, s0, 1); s0 += __shfl_xor_sync(0xffffffffu, s0, 2);
    q0 += __shfl_xor_sync(0xffffffffu, q0, 1); q0 += __shfl_xor_sync(0xffffffffu, q0, 2);
    s1 += __shfl_xor_sync(0xffffffffu, s1, 1); s1 += __shfl_xor_sync(0xffffffffu, s1, 2);
    q1 += __shfl_xor_sync(0xffffffffu, q1, 1); q1 += __shfl_xor_sync(0xffffffffu, q1, 2);
    float mu0 = s0*(1.f/128.f), mu1 = s1*(1.f/128.f);
    float rs0 = rsqrtf(fmaxf(q0*(1.f/128.f) - mu0*mu0, 0.f) + EPS_);
    float rs1 = rsqrtf(fmaxf(q1*(1.f/128.f) - mu1*mu1, 0.f) + EPS_);
    #pragma unroll
    for (int nt = 0; nt < 16; nt++) {
        int col = nt*8 + 2*tg;
        float2 gg = *reinterpret_cast<const float2*>(&lg[col]);
        float2 bb = *reinterpret_cast<const float2*>(&lb[col]);
        *reinterpret_cast<float2*>(&out[r0*F_ + col]) = make_float2(
            (D[nt][0]-mu0)*rs0*gg.x + bb.x, (D[nt][1]-mu0)*rs0*gg.y + bb.y);
        *reinterpret_cast<float2*>(&out[r1*F_ + col]) = make_float2(
            (D[nt][2]-mu1)*rs1*gg.x + bb.x, (D[nt][3]-mu1)*rs1*gg.y + bb.y);
    }
}

extern "C" void kernel_launch(void* const* d_in, const int* in_sizes, int n_in,
                              void* d_out, int out_size) {
    const float* input = (const float*)d_in[0];
    const float* W_xff = (const float*)d_in[1];
    const float* b_xff = (const float*)d_in[2];
    const float* W_ff1 = (const float*)d_in[3];
    const float* b_ff1 = (const float*)d_in[4];
    const float* W_ff2 = (const float*)d_in[5];
    const float* b_ff2 = (const float*)d_in[6];
    const float* ln_g  = (const float*)d_in[7];
    const float* ln_b  = (const float*)d_in[8];
    float* out = (float*)d_out;

    const int smQKV = 2*128*132*4;                    // 135168
    const int smCOL = (16*1024 + 16*LDP + 64*LDP)*4;  // 107776
    const int smATT = (3*64*132 + 64)*4;              // 101632
    const int smFF  = 3*128*132*4;                    // 202752
    cudaFuncSetAttribute(k_qkv_mma,  cudaFuncAttributeMaxDynamicSharedMemorySize, smQKV);
    cudaFuncSetAttribute(k_colsum,   cudaFuncAttributeMaxDynamicSharedMemorySize, smCOL);
    cudaFuncSetAttribute(k_attn_mma, cudaFuncAttributeMaxDynamicSharedMemorySize, smATT);
    cudaFuncSetAttribute(k_ffln_mma, cudaFuncAttributeMaxDynamicSharedMemorySize, smFF);

    k_zero<<<16, 256>>>();
    k_qkv_mma<<<dim3(ROWS_TOT/128, 3), 256, smQKV>>>(input, W_xff, b_xff);
    k_colsum<<<dim3(N_/16, B_), 256, smCOL>>>();
    k_ylast<<<B_, 256>>>();
    k_mixup<<<B_*FRONT_T_, F_>>>();
    k_attn_mma<<<dim3(N_/64, H_), 256, smATT>>>();
    k_ffln_mma<<<ROWS_TOT/128, 256, smFF>>>(input, W_ff1, b_ff1, W_ff2, b_ff2,
                                            ln_g, ln_b, out);
}